// round 3
// baseline (speedup 1.0000x reference)
#include <cuda_runtime.h>
#include <cuda_bf16.h>
#include <math.h>

#define N_NODES  100000
#define N_EDGES  1600000
#define N_GRAPHS 512
#define F_IN     20
#define HID      128
#define OUT_F    64

// ---------------- static device scratch (no runtime allocation) ----------------
__device__ int    g_cnt[N_NODES];
__device__ int    g_fill[N_NODES];
__device__ int    g_rowptr[N_NODES + 1];
__device__ float  g_dinv[N_NODES];
__device__ int    g_col[N_EDGES];
__device__ float  g_w[N_EDGES];
__device__ float  g_aggx[N_NODES * F_IN];
__device__ float4 g_bufA[(size_t)N_NODES * (HID / 4)];   // [N,128] as float4
__device__ float4 g_bufB[(size_t)N_NODES * (HID / 4)];
__device__ int    g_gstart[N_GRAPHS + 1];
__device__ float  g_pool[N_GRAPHS * HID];

// ---------------- kernels ----------------

__global__ void zero_k() {
    int i = blockIdx.x * blockDim.x + threadIdx.x;
    if (i < N_NODES) { g_cnt[i] = 0; g_fill[i] = 0; }
}

__global__ void hist_k(const int* __restrict__ ei) {
    int e = blockIdx.x * blockDim.x + threadIdx.x;
    if (e < N_EDGES) {
        int d = ei[N_EDGES + e];
        atomicAdd(&g_cnt[d], 1);
    }
}

__global__ void dinv_k() {
    int i = blockIdx.x * blockDim.x + threadIdx.x;
    if (i < N_NODES) {
        g_dinv[i] = rsqrtf((float)(g_cnt[i] + 1));  // +1 self loop
    }
}

// single block, 1024 threads: exclusive scan of g_cnt -> g_rowptr
__global__ void scan_k() {
    __shared__ int wsum[32];
    __shared__ int s_carry;
    int tid = threadIdx.x, lane = tid & 31, wid = tid >> 5;
    if (tid == 0) s_carry = 0;
    __syncthreads();
    for (int off = 0; off < N_NODES; off += 1024) {
        int i = off + tid;
        int v = (i < N_NODES) ? g_cnt[i] : 0;
        int xv = v;
#pragma unroll
        for (int d = 1; d < 32; d <<= 1) {
            int t = __shfl_up_sync(0xffffffffu, xv, d);
            if (lane >= d) xv += t;
        }
        if (lane == 31) wsum[wid] = xv;
        __syncthreads();
        if (wid == 0) {
            int y = wsum[lane];
#pragma unroll
            for (int d = 1; d < 32; d <<= 1) {
                int t = __shfl_up_sync(0xffffffffu, y, d);
                if (lane >= d) y += t;
            }
            wsum[lane] = y;
        }
        __syncthreads();
        int incl = xv + (wid > 0 ? wsum[wid - 1] : 0);
        int carry = s_carry;
        if (i < N_NODES) g_rowptr[i] = carry + incl - v;
        __syncthreads();
        if (tid == 1023) s_carry = carry + wsum[31];
        __syncthreads();
    }
    if (threadIdx.x == 0) g_rowptr[N_NODES] = s_carry;
}

__global__ void fill_k(const int* __restrict__ ei) {
    int e = blockIdx.x * blockDim.x + threadIdx.x;
    if (e < N_EDGES) {
        int s = ei[e];
        int d = ei[N_EDGES + e];
        int p = g_rowptr[d] + atomicAdd(&g_fill[d], 1);
        g_col[p] = s;
        g_w[p] = g_dinv[s];
    }
}

// graph segment boundaries from sorted batch (int32)
__global__ void bounds_k(const int* __restrict__ batch) {
    int i = blockIdx.x * blockDim.x + threadIdx.x;
    if (i >= N_NODES) return;
    int b = batch[i];
    if (i == 0) {
        for (int g = 0; g <= b; g++) g_gstart[g] = 0;
    }
    int bn = (i + 1 < N_NODES) ? batch[i + 1] : N_GRAPHS;
    for (int g = b + 1; g <= bn; g++) g_gstart[g] = i + 1;
}

// warp per node: aggregate raw x (20 dims)
__global__ __launch_bounds__(256) void agg20_k(const float* __restrict__ x) {
    int warp = (blockIdx.x * blockDim.x + threadIdx.x) >> 5;
    int lane = threadIdx.x & 31;
    if (warp >= N_NODES) return;
    int beg = g_rowptr[warp], end = g_rowptr[warp + 1];
    float di = g_dinv[warp];
    float acc = 0.0f;
    if (lane < F_IN) acc = di * x[(size_t)warp * F_IN + lane];
    for (int e = beg; e < end; e++) {
        int s = g_col[e];
        float w = g_w[e];
        if (lane < F_IN) acc += w * x[(size_t)s * F_IN + lane];
    }
    if (lane < F_IN) g_aggx[(size_t)warp * F_IN + lane] = di * acc;
}

// [N,20] @ [20,128] + b, relu -> g_bufA
__global__ __launch_bounds__(128) void gemm20_k(const float* __restrict__ W1,
                                                const float* __restrict__ b1) {
    __shared__ float sW[F_IN * HID];
    __shared__ float sB[HID];
    int tid = threadIdx.x;
    for (int i = tid; i < F_IN * HID; i += 128) sW[i] = W1[i];
    sB[tid] = b1[tid];
    __syncthreads();
    float* Y = (float*)g_bufA;
    int base = blockIdx.x * 64;
    for (int j = 0; j < 64; j++) {
        int node = base + j;
        if (node >= N_NODES) return;
        float acc = sB[tid];
#pragma unroll
        for (int k = 0; k < F_IN; k++)
            acc = fmaf(g_aggx[(size_t)node * F_IN + k], sW[k * HID + tid], acc);
        Y[(size_t)node * HID + tid] = fmaxf(acc, 0.0f);
    }
}

// warp per node: aggregate 128-dim features. src_is_A=1: A->B else B->A.
__global__ __launch_bounds__(256) void agg128_k(int src_is_A) {
    int warp = (blockIdx.x * blockDim.x + threadIdx.x) >> 5;
    int lane = threadIdx.x & 31;
    if (warp >= N_NODES) return;
    const float4* H4 = src_is_A ? g_bufA : g_bufB;
    float4* O4 = src_is_A ? g_bufB : g_bufA;
    int beg = g_rowptr[warp], end = g_rowptr[warp + 1];
    float di = g_dinv[warp];
    float4 acc;
    {   // self loop
        float4 v = H4[(size_t)warp * 32 + lane];
        acc.x = di * v.x; acc.y = di * v.y; acc.z = di * v.z; acc.w = di * v.w;
    }
    for (int e = beg; e < end; e++) {
        int s = g_col[e];
        float w = g_w[e];
        float4 v = H4[(size_t)s * 32 + lane];
        acc.x = fmaf(w, v.x, acc.x); acc.y = fmaf(w, v.y, acc.y);
        acc.z = fmaf(w, v.z, acc.z); acc.w = fmaf(w, v.w, acc.w);
    }
    float4 o;
    o.x = di * acc.x; o.y = di * acc.y; o.z = di * acc.z; o.w = di * acc.w;
    O4[(size_t)warp * 32 + lane] = o;
}

#define FMA4(ACC, A, W) { ACC.x = fmaf((A),(W).x,ACC.x); ACC.y = fmaf((A),(W).y,ACC.y); \
                          ACC.z = fmaf((A),(W).z,ACC.z); ACC.w = fmaf((A),(W).w,ACC.w); }

// [N,128] @ [128,128] + b, relu.  src_is_A=1: read A write B, else B->A.
// Static smem: 64-node A tile (32KB). W streamed from global (L1/L2-resident, broadcast).
__global__ __launch_bounds__(256) void gemm128_k(const float* __restrict__ W,
                                                 const float* __restrict__ bias,
                                                 int src_is_A) {
    __shared__ float4 sA[64 * 32];             // 32 KB
    const float4* A4 = src_is_A ? g_bufA : g_bufB;
    float4* Y4 = src_is_A ? g_bufB : g_bufA;
    const float4* W4 = (const float4*)W;

    int tid = threadIdx.x;
    int lane = tid & 31, wid = tid >> 5;       // 8 warps, 8 nodes each
    int base = blockIdx.x * 64;

    for (int i = tid; i < 64 * 32; i += 256) {
        int row = i >> 5, q = i & 31;
        int node = base + row;
        sA[i] = (node < N_NODES) ? A4[(size_t)node * 32 + q]
                                 : make_float4(0.f, 0.f, 0.f, 0.f);
    }
    __syncthreads();

    int r0 = wid * 8;
    float4 acc[8];
#pragma unroll
    for (int j = 0; j < 8; j++) acc[j] = make_float4(0.f, 0.f, 0.f, 0.f);

#pragma unroll 2
    for (int k4 = 0; k4 < 32; k4++) {
        float4 a[8];
#pragma unroll
        for (int j = 0; j < 8; j++) a[j] = sA[(r0 + j) * 32 + k4];  // smem broadcast
        float4 w;
        w = W4[(k4 * 4 + 0) * 32 + lane];
#pragma unroll
        for (int j = 0; j < 8; j++) FMA4(acc[j], a[j].x, w)
        w = W4[(k4 * 4 + 1) * 32 + lane];
#pragma unroll
        for (int j = 0; j < 8; j++) FMA4(acc[j], a[j].y, w)
        w = W4[(k4 * 4 + 2) * 32 + lane];
#pragma unroll
        for (int j = 0; j < 8; j++) FMA4(acc[j], a[j].z, w)
        w = W4[(k4 * 4 + 3) * 32 + lane];
#pragma unroll
        for (int j = 0; j < 8; j++) FMA4(acc[j], a[j].w, w)
    }

    float4 b4 = ((const float4*)bias)[lane];
#pragma unroll
    for (int j = 0; j < 8; j++) {
        int node = base + r0 + j;
        if (node < N_NODES) {
            float4 o = acc[j];
            o.x = fmaxf(o.x + b4.x, 0.f);
            o.y = fmaxf(o.y + b4.y, 0.f);
            o.z = fmaxf(o.z + b4.z, 0.f);
            o.w = fmaxf(o.w + b4.w, 0.f);
            Y4[(size_t)node * 32 + lane] = o;
        }
    }
}

// mean pool per graph: block per graph, thread per channel (reads g_bufA)
__global__ __launch_bounds__(128) void pool_k() {
    int g = blockIdx.x;
    int c = threadIdx.x;
    int s = g_gstart[g], e = g_gstart[g + 1];
    const float* H = (const float*)g_bufA;
    float acc = 0.0f;
    for (int n = s; n < e; n++) acc += H[(size_t)n * HID + c];
    float inv = 1.0f / fmaxf((float)(e - s), 1.0f);
    g_pool[g * HID + c] = acc * inv;
}

// [512,128] @ [128,64] + bout -> out
__global__ __launch_bounds__(64) void head_k(const float* __restrict__ Wout,
                                             const float* __restrict__ bout,
                                             float* __restrict__ out) {
    int g = blockIdx.x;
    int o = threadIdx.x;
    float acc = bout[o];
#pragma unroll 8
    for (int c = 0; c < HID; c++)
        acc = fmaf(g_pool[g * HID + c], Wout[c * OUT_F + o], acc);
    out[g * OUT_F + o] = acc;
}

// ---------------- launch (kernel launches ONLY — graph-capture safe) ----------------
extern "C" void kernel_launch(void* const* d_in, const int* in_sizes, int n_in,
                              void* d_out, int out_size) {
    const float* x     = (const float*)d_in[0];
    const int*   ei    = (const int*)d_in[1];    // int32! (JAX x64 disabled)
    const int*   batch = (const int*)d_in[2];    // int32!
    const float* W1 = (const float*)d_in[3];
    const float* b1 = (const float*)d_in[4];
    const float* W2 = (const float*)d_in[5];
    const float* b2 = (const float*)d_in[6];
    const float* W3 = (const float*)d_in[7];
    const float* b3 = (const float*)d_in[8];
    const float* Wout = (const float*)d_in[9];
    const float* bout = (const float*)d_in[10];
    float* out = (float*)d_out;

    const int NB = 256;
    int nblk_nodes = (N_NODES + NB - 1) / NB;
    int nblk_edges = (N_EDGES + NB - 1) / NB;
    int nblk_warpnode = (N_NODES * 32 + NB - 1) / NB;
    int nblk_gemm = (N_NODES + 63) / 64;

    // build CSR + norms
    zero_k<<<nblk_nodes, NB>>>();
    hist_k<<<nblk_edges, NB>>>(ei);
    dinv_k<<<nblk_nodes, NB>>>();
    scan_k<<<1, 1024>>>();
    fill_k<<<nblk_edges, NB>>>(ei);
    bounds_k<<<nblk_nodes, NB>>>(batch);

    // layer 1: aggregate x (20 dims), then GEMM+bias+relu -> bufA
    agg20_k<<<nblk_warpnode, NB>>>(x);
    gemm20_k<<<nblk_gemm, 128>>>(W1, b1);

    // layer 2: A -(agg)-> B -(gemm)-> A
    agg128_k<<<nblk_warpnode, NB>>>(1);
    gemm128_k<<<nblk_gemm, 256>>>(W2, b2, 0);

    // layer 3
    agg128_k<<<nblk_warpnode, NB>>>(1);
    gemm128_k<<<nblk_gemm, 256>>>(W3, b3, 0);

    // pool + head (pool reads bufA)
    pool_k<<<N_GRAPHS, HID>>>();
    head_k<<<N_GRAPHS, OUT_F>>>(Wout, bout, out);
}

// round 4
// speedup vs baseline: 1.0988x; 1.0988x over previous
#include <cuda_runtime.h>
#include <cuda_bf16.h>
#include <math.h>

#define N_NODES  100000
#define N_EDGES  1600000
#define N_GRAPHS 512
#define F_IN     20
#define HID      128
#define OUT_F    64
#define NBLK_SCAN ((N_NODES + 1023) / 1024)   // 98

// ---------------- static device scratch (no runtime allocation) ----------------
__device__ int    g_cnt[N_NODES];
__device__ int    g_fill[N_NODES];
__device__ int    g_rowptr[N_NODES + 1];
__device__ float  g_dinv[N_NODES];
__device__ int    g_col[N_EDGES];
__device__ float  g_w[N_EDGES];
__device__ float  g_aggx[N_NODES * F_IN];
__device__ float4 g_bufA[(size_t)N_NODES * (HID / 4)];   // [N,128] as float4
__device__ float4 g_bufB[(size_t)N_NODES * (HID / 4)];
__device__ int    g_gstart[N_GRAPHS + 1];
__device__ float  g_pool[N_GRAPHS * HID];
__device__ int    g_bsum[NBLK_SCAN];
__device__ int    g_boff[NBLK_SCAN];

// ---------------- kernels ----------------

__global__ void zero_k() {
    int i = blockIdx.x * blockDim.x + threadIdx.x;
    if (i < N_NODES) { g_cnt[i] = 0; g_fill[i] = 0; }
}

__global__ void hist_k(const int* __restrict__ ei) {
    int e = blockIdx.x * blockDim.x + threadIdx.x;
    if (e < N_EDGES) {
        int d = ei[N_EDGES + e];
        atomicAdd(&g_cnt[d], 1);
    }
}

__global__ void dinv_k() {
    int i = blockIdx.x * blockDim.x + threadIdx.x;
    if (i < N_NODES) {
        g_dinv[i] = rsqrtf((float)(g_cnt[i] + 1));  // +1 self loop
    }
}

// ---- hierarchical exclusive scan of g_cnt -> g_rowptr ----
// pass 1: per-block (1024 elems) local exclusive scan + block sums
__global__ __launch_bounds__(1024) void scan1_k() {
    __shared__ int wsum[32];
    int tid = threadIdx.x, lane = tid & 31, wid = tid >> 5;
    int i = blockIdx.x * 1024 + tid;
    int v = (i < N_NODES) ? g_cnt[i] : 0;
    int xv = v;
#pragma unroll
    for (int d = 1; d < 32; d <<= 1) {
        int t = __shfl_up_sync(0xffffffffu, xv, d);
        if (lane >= d) xv += t;
    }
    if (lane == 31) wsum[wid] = xv;
    __syncthreads();
    if (wid == 0) {
        int y = wsum[lane];
#pragma unroll
        for (int d = 1; d < 32; d <<= 1) {
            int t = __shfl_up_sync(0xffffffffu, y, d);
            if (lane >= d) y += t;
        }
        wsum[lane] = y;
    }
    __syncthreads();
    int incl = xv + (wid > 0 ? wsum[wid - 1] : 0);
    if (i < N_NODES) g_rowptr[i] = incl - v;     // block-local exclusive
    if (tid == 1023) g_bsum[blockIdx.x] = incl;  // block total
}

// pass 2: single block scans the 98 block sums (exclusive) + writes total
__global__ __launch_bounds__(128) void scan2_k() {
    __shared__ int wsum[4];
    int tid = threadIdx.x, lane = tid & 31, wid = tid >> 5;
    int v = (tid < NBLK_SCAN) ? g_bsum[tid] : 0;
    int xv = v;
#pragma unroll
    for (int d = 1; d < 32; d <<= 1) {
        int t = __shfl_up_sync(0xffffffffu, xv, d);
        if (lane >= d) xv += t;
    }
    if (lane == 31) wsum[wid] = xv;
    __syncthreads();
    int pre = 0;
    for (int w = 0; w < wid; w++) pre += wsum[w];
    int incl = xv + pre;
    if (tid < NBLK_SCAN) g_boff[tid] = incl - v;
    if (tid == 127) g_rowptr[N_NODES] = incl;    // grand total
}

// pass 3: add block offsets
__global__ __launch_bounds__(1024) void scan3_k() {
    int i = blockIdx.x * 1024 + threadIdx.x;
    if (i < N_NODES) g_rowptr[i] += g_boff[blockIdx.x];
}

__global__ void fill_k(const int* __restrict__ ei) {
    int e = blockIdx.x * blockDim.x + threadIdx.x;
    if (e < N_EDGES) {
        int s = ei[e];
        int d = ei[N_EDGES + e];
        int p = g_rowptr[d] + atomicAdd(&g_fill[d], 1);
        g_col[p] = s;
        g_w[p] = g_dinv[s];
    }
}

// graph segment boundaries from sorted batch (int32)
__global__ void bounds_k(const int* __restrict__ batch) {
    int i = blockIdx.x * blockDim.x + threadIdx.x;
    if (i >= N_NODES) return;
    int b = batch[i];
    if (i == 0) {
        for (int g = 0; g <= b; g++) g_gstart[g] = 0;
    }
    int bn = (i + 1 < N_NODES) ? batch[i + 1] : N_GRAPHS;
    for (int g = b + 1; g <= bn; g++) g_gstart[g] = i + 1;
}

// warp per node: aggregate raw x (20 dims)
__global__ __launch_bounds__(256) void agg20_k(const float* __restrict__ x) {
    int warp = (blockIdx.x * blockDim.x + threadIdx.x) >> 5;
    int lane = threadIdx.x & 31;
    if (warp >= N_NODES) return;
    int beg = g_rowptr[warp], end = g_rowptr[warp + 1];
    float di = g_dinv[warp];
    float acc = 0.0f;
    if (lane < F_IN) acc = di * x[(size_t)warp * F_IN + lane];
    for (int e = beg; e < end; e++) {
        int s = g_col[e];
        float w = g_w[e];
        if (lane < F_IN) acc += w * x[(size_t)s * F_IN + lane];
    }
    if (lane < F_IN) g_aggx[(size_t)warp * F_IN + lane] = di * acc;
}

// [N,20] @ [20,128] + b, relu -> g_bufA
__global__ __launch_bounds__(128) void gemm20_k(const float* __restrict__ W1,
                                                const float* __restrict__ b1) {
    __shared__ float sW[F_IN * HID];
    __shared__ float sB[HID];
    int tid = threadIdx.x;
    for (int i = tid; i < F_IN * HID; i += 128) sW[i] = W1[i];
    sB[tid] = b1[tid];
    __syncthreads();
    float* Y = (float*)g_bufA;
    int base = blockIdx.x * 64;
    for (int j = 0; j < 64; j++) {
        int node = base + j;
        if (node >= N_NODES) return;
        float acc = sB[tid];
#pragma unroll
        for (int k = 0; k < F_IN; k++)
            acc = fmaf(g_aggx[(size_t)node * F_IN + k], sW[k * HID + tid], acc);
        Y[(size_t)node * HID + tid] = fmaxf(acc, 0.0f);
    }
}

// warp per node: aggregate 128-dim features. src_is_A=1: A->B else B->A.
__global__ __launch_bounds__(256) void agg128_k(int src_is_A) {
    int warp = (blockIdx.x * blockDim.x + threadIdx.x) >> 5;
    int lane = threadIdx.x & 31;
    if (warp >= N_NODES) return;
    const float4* H4 = src_is_A ? g_bufA : g_bufB;
    float4* O4 = src_is_A ? g_bufB : g_bufA;
    int beg = g_rowptr[warp], end = g_rowptr[warp + 1];
    float di = g_dinv[warp];
    float4 acc;
    {   // self loop
        float4 v = H4[(size_t)warp * 32 + lane];
        acc.x = di * v.x; acc.y = di * v.y; acc.z = di * v.z; acc.w = di * v.w;
    }
    for (int e = beg; e < end; e++) {
        int s = g_col[e];
        float w = g_w[e];
        float4 v = H4[(size_t)s * 32 + lane];
        acc.x = fmaf(w, v.x, acc.x); acc.y = fmaf(w, v.y, acc.y);
        acc.z = fmaf(w, v.z, acc.z); acc.w = fmaf(w, v.w, acc.w);
    }
    float4 o;
    o.x = di * acc.x; o.y = di * acc.y; o.z = di * acc.z; o.w = di * acc.w;
    O4[(size_t)warp * 32 + lane] = o;
}

#define FMA4(ACC, A, W) { ACC.x = fmaf((A),(W).x,ACC.x); ACC.y = fmaf((A),(W).y,ACC.y); \
                          ACC.z = fmaf((A),(W).z,ACC.z); ACC.w = fmaf((A),(W).w,ACC.w); }

// [N,128] @ [128,128] + b, relu.  src_is_A=1: read A write B, else B->A.
__global__ __launch_bounds__(256) void gemm128_k(const float* __restrict__ W,
                                                 const float* __restrict__ bias,
                                                 int src_is_A) {
    __shared__ float4 sA[64 * 32];             // 32 KB
    const float4* A4 = src_is_A ? g_bufA : g_bufB;
    float4* Y4 = src_is_A ? g_bufB : g_bufA;
    const float4* W4 = (const float4*)W;

    int tid = threadIdx.x;
    int lane = tid & 31, wid = tid >> 5;       // 8 warps, 8 nodes each
    int base = blockIdx.x * 64;

    for (int i = tid; i < 64 * 32; i += 256) {
        int row = i >> 5, q = i & 31;
        int node = base + row;
        sA[i] = (node < N_NODES) ? A4[(size_t)node * 32 + q]
                                 : make_float4(0.f, 0.f, 0.f, 0.f);
    }
    __syncthreads();

    int r0 = wid * 8;
    float4 acc[8];
#pragma unroll
    for (int j = 0; j < 8; j++) acc[j] = make_float4(0.f, 0.f, 0.f, 0.f);

#pragma unroll 2
    for (int k4 = 0; k4 < 32; k4++) {
        float4 a[8];
#pragma unroll
        for (int j = 0; j < 8; j++) a[j] = sA[(r0 + j) * 32 + k4];  // smem broadcast
        float4 w;
        w = W4[(k4 * 4 + 0) * 32 + lane];
#pragma unroll
        for (int j = 0; j < 8; j++) FMA4(acc[j], a[j].x, w)
        w = W4[(k4 * 4 + 1) * 32 + lane];
#pragma unroll
        for (int j = 0; j < 8; j++) FMA4(acc[j], a[j].y, w)
        w = W4[(k4 * 4 + 2) * 32 + lane];
#pragma unroll
        for (int j = 0; j < 8; j++) FMA4(acc[j], a[j].z, w)
        w = W4[(k4 * 4 + 3) * 32 + lane];
#pragma unroll
        for (int j = 0; j < 8; j++) FMA4(acc[j], a[j].w, w)
    }

    float4 b4 = ((const float4*)bias)[lane];
#pragma unroll
    for (int j = 0; j < 8; j++) {
        int node = base + r0 + j;
        if (node < N_NODES) {
            float4 o = acc[j];
            o.x = fmaxf(o.x + b4.x, 0.f);
            o.y = fmaxf(o.y + b4.y, 0.f);
            o.z = fmaxf(o.z + b4.z, 0.f);
            o.w = fmaxf(o.w + b4.w, 0.f);
            Y4[(size_t)node * 32 + lane] = o;
        }
    }
}

// mean pool per graph: block per graph, thread per channel (reads g_bufA)
__global__ __launch_bounds__(128) void pool_k() {
    int g = blockIdx.x;
    int c = threadIdx.x;
    int s = g_gstart[g], e = g_gstart[g + 1];
    const float* H = (const float*)g_bufA;
    float acc = 0.0f;
    for (int n = s; n < e; n++) acc += H[(size_t)n * HID + c];
    float inv = 1.0f / fmaxf((float)(e - s), 1.0f);
    g_pool[g * HID + c] = acc * inv;
}

// [512,128] @ [128,64] + bout -> out
__global__ __launch_bounds__(64) void head_k(const float* __restrict__ Wout,
                                             const float* __restrict__ bout,
                                             float* __restrict__ out) {
    int g = blockIdx.x;
    int o = threadIdx.x;
    float acc = bout[o];
#pragma unroll 8
    for (int c = 0; c < HID; c++)
        acc = fmaf(g_pool[g * HID + c], Wout[c * OUT_F + o], acc);
    out[g * OUT_F + o] = acc;
}

// ---------------- launch (kernel launches ONLY — graph-capture safe) ----------------
extern "C" void kernel_launch(void* const* d_in, const int* in_sizes, int n_in,
                              void* d_out, int out_size) {
    const float* x     = (const float*)d_in[0];
    const int*   ei    = (const int*)d_in[1];    // int32 (JAX x64 disabled)
    const int*   batch = (const int*)d_in[2];    // int32
    const float* W1 = (const float*)d_in[3];
    const float* b1 = (const float*)d_in[4];
    const float* W2 = (const float*)d_in[5];
    const float* b2 = (const float*)d_in[6];
    const float* W3 = (const float*)d_in[7];
    const float* b3 = (const float*)d_in[8];
    const float* Wout = (const float*)d_in[9];
    const float* bout = (const float*)d_in[10];
    float* out = (float*)d_out;

    const int NB = 256;
    int nblk_nodes = (N_NODES + NB - 1) / NB;
    int nblk_edges = (N_EDGES + NB - 1) / NB;
    int nblk_warpnode = (N_NODES * 32 + NB - 1) / NB;
    int nblk_gemm = (N_NODES + 63) / 64;

    // build CSR + norms
    zero_k<<<nblk_nodes, NB>>>();
    hist_k<<<nblk_edges, NB>>>(ei);
    dinv_k<<<nblk_nodes, NB>>>();
    scan1_k<<<NBLK_SCAN, 1024>>>();
    scan2_k<<<1, 128>>>();
    scan3_k<<<NBLK_SCAN, 1024>>>();
    fill_k<<<nblk_edges, NB>>>(ei);
    bounds_k<<<nblk_nodes, NB>>>(batch);

    // layer 1: aggregate x (20 dims), then GEMM+bias+relu -> bufA
    agg20_k<<<nblk_warpnode, NB>>>(x);
    gemm20_k<<<nblk_gemm, 128>>>(W1, b1);

    // layer 2: A -(agg)-> B -(gemm)-> A
    agg128_k<<<nblk_warpnode, NB>>>(1);
    gemm128_k<<<nblk_gemm, 256>>>(W2, b2, 0);

    // layer 3
    agg128_k<<<nblk_warpnode, NB>>>(1);
    gemm128_k<<<nblk_gemm, 256>>>(W3, b3, 0);

    // pool + head (pool reads bufA)
    pool_k<<<N_GRAPHS, HID>>>();
    head_k<<<N_GRAPHS, OUT_F>>>(Wout, bout, out);
}

// round 6
// speedup vs baseline: 1.1792x; 1.0731x over previous
#include <cuda_runtime.h>
#include <cuda_bf16.h>
#include <math.h>

#define N_NODES  100000
#define N_EDGES  1600000
#define N_GRAPHS 512
#define F_IN     20
#define HID      128
#define OUT_F    64
#define NBLK_SCAN ((N_NODES + 1023) / 1024)   // 98

// ---------------- static device scratch (no runtime allocation) ----------------
__device__ int    g_cnt[N_NODES];
__device__ int    g_fill[N_NODES];
__device__ int    g_rowptr[N_NODES + 1];
__device__ float  g_dinv[N_NODES];
__device__ int    g_col[N_EDGES];
__device__ float  g_w[N_EDGES];
__device__ float  g_aggx[N_NODES * F_IN];
__device__ float4 g_bufA[(size_t)N_NODES * (HID / 4)];   // [N,128] as float4
__device__ float4 g_bufB[(size_t)N_NODES * (HID / 4)];
__device__ int    g_gstart[N_GRAPHS + 1];
__device__ float  g_pool[N_GRAPHS * HID];
__device__ int    g_bsum[NBLK_SCAN];
__device__ int    g_boff[NBLK_SCAN];

// ---------------- helpers ----------------
__device__ __forceinline__ float tf32r(float x) {
    float y;
    asm("cvt.rna.tf32.f32 %0, %1;" : "=f"(y) : "f"(x));
    return y;
}

// ---------------- kernels ----------------

__global__ void zero_k() {
    int i = blockIdx.x * blockDim.x + threadIdx.x;
    if (i < N_NODES) { g_cnt[i] = 0; g_fill[i] = 0; }
}

__global__ void hist_k(const int* __restrict__ ei) {
    int e = blockIdx.x * blockDim.x + threadIdx.x;
    if (e < N_EDGES) {
        int d = ei[N_EDGES + e];
        atomicAdd(&g_cnt[d], 1);
    }
}

__global__ void dinv_k() {
    int i = blockIdx.x * blockDim.x + threadIdx.x;
    if (i < N_NODES) {
        g_dinv[i] = rsqrtf((float)(g_cnt[i] + 1));  // +1 self loop
    }
}

// ---- hierarchical exclusive scan of g_cnt -> g_rowptr ----
__global__ __launch_bounds__(1024) void scan1_k() {
    __shared__ int wsum[32];
    int tid = threadIdx.x, lane = tid & 31, wid = tid >> 5;
    int i = blockIdx.x * 1024 + tid;
    int v = (i < N_NODES) ? g_cnt[i] : 0;
    int xv = v;
#pragma unroll
    for (int d = 1; d < 32; d <<= 1) {
        int t = __shfl_up_sync(0xffffffffu, xv, d);
        if (lane >= d) xv += t;
    }
    if (lane == 31) wsum[wid] = xv;
    __syncthreads();
    if (wid == 0) {
        int y = wsum[lane];
#pragma unroll
        for (int d = 1; d < 32; d <<= 1) {
            int t = __shfl_up_sync(0xffffffffu, y, d);
            if (lane >= d) y += t;
        }
        wsum[lane] = y;
    }
    __syncthreads();
    int incl = xv + (wid > 0 ? wsum[wid - 1] : 0);
    if (i < N_NODES) g_rowptr[i] = incl - v;
    if (tid == 1023) g_bsum[blockIdx.x] = incl;
}

__global__ __launch_bounds__(128) void scan2_k() {
    __shared__ int wsum[4];
    int tid = threadIdx.x, lane = tid & 31, wid = tid >> 5;
    int v = (tid < NBLK_SCAN) ? g_bsum[tid] : 0;
    int xv = v;
#pragma unroll
    for (int d = 1; d < 32; d <<= 1) {
        int t = __shfl_up_sync(0xffffffffu, xv, d);
        if (lane >= d) xv += t;
    }
    if (lane == 31) wsum[wid] = xv;
    __syncthreads();
    int pre = 0;
    for (int w = 0; w < wid; w++) pre += wsum[w];
    int incl = xv + pre;
    if (tid < NBLK_SCAN) g_boff[tid] = incl - v;
    if (tid == 127) g_rowptr[N_NODES] = incl;
}

__global__ __launch_bounds__(1024) void scan3_k() {
    int i = blockIdx.x * 1024 + threadIdx.x;
    if (i < N_NODES) g_rowptr[i] += g_boff[blockIdx.x];
}

__global__ void fill_k(const int* __restrict__ ei) {
    int e = blockIdx.x * blockDim.x + threadIdx.x;
    if (e < N_EDGES) {
        int s = ei[e];
        int d = ei[N_EDGES + e];
        int p = g_rowptr[d] + atomicAdd(&g_fill[d], 1);
        g_col[p] = s;
        g_w[p] = g_dinv[s];
    }
}

__global__ void bounds_k(const int* __restrict__ batch) {
    int i = blockIdx.x * blockDim.x + threadIdx.x;
    if (i >= N_NODES) return;
    int b = batch[i];
    if (i == 0) {
        for (int g = 0; g <= b; g++) g_gstart[g] = 0;
    }
    int bn = (i + 1 < N_NODES) ? batch[i + 1] : N_GRAPHS;
    for (int g = b + 1; g <= bn; g++) g_gstart[g] = i + 1;
}

// warp per node: aggregate raw x (20 dims)
__global__ __launch_bounds__(256) void agg20_k(const float* __restrict__ x) {
    int warp = (blockIdx.x * blockDim.x + threadIdx.x) >> 5;
    int lane = threadIdx.x & 31;
    if (warp >= N_NODES) return;
    int beg = g_rowptr[warp], end = g_rowptr[warp + 1];
    float di = g_dinv[warp];
    float acc = 0.0f;
    if (lane < F_IN) acc = di * x[(size_t)warp * F_IN + lane];
    for (int e = beg; e < end; e++) {
        int s = g_col[e];
        float w = g_w[e];
        if (lane < F_IN) acc += w * x[(size_t)s * F_IN + lane];
    }
    if (lane < F_IN) g_aggx[(size_t)warp * F_IN + lane] = di * acc;
}

// [N,20] @ [20,128] + b, relu -> g_bufA   (fp32, layer-1 K is tiny)
__global__ __launch_bounds__(128) void gemm20_k(const float* __restrict__ W1,
                                                const float* __restrict__ b1) {
    __shared__ float sW[F_IN * HID];
    __shared__ float sB[HID];
    int tid = threadIdx.x;
    for (int i = tid; i < F_IN * HID; i += 128) sW[i] = W1[i];
    sB[tid] = b1[tid];
    __syncthreads();
    float* Y = (float*)g_bufA;
    int base = blockIdx.x * 64;
    for (int j = 0; j < 64; j++) {
        int node = base + j;
        if (node >= N_NODES) return;
        float acc = sB[tid];
#pragma unroll
        for (int k = 0; k < F_IN; k++)
            acc = fmaf(g_aggx[(size_t)node * F_IN + k], sW[k * HID + tid], acc);
        Y[(size_t)node * HID + tid] = fmaxf(acc, 0.0f);
    }
}

// warp per node: aggregate 128-dim features. src_is_A=1: A->B else B->A.
__global__ __launch_bounds__(256) void agg128_k(int src_is_A) {
    int warp = (blockIdx.x * blockDim.x + threadIdx.x) >> 5;
    int lane = threadIdx.x & 31;
    if (warp >= N_NODES) return;
    const float4* H4 = src_is_A ? g_bufA : g_bufB;
    float4* O4 = src_is_A ? g_bufB : g_bufA;
    int beg = g_rowptr[warp], end = g_rowptr[warp + 1];
    float di = g_dinv[warp];
    float4 acc;
    {
        float4 v = H4[(size_t)warp * 32 + lane];
        acc.x = di * v.x; acc.y = di * v.y; acc.z = di * v.z; acc.w = di * v.w;
    }
    for (int e = beg; e < end; e++) {
        int s = g_col[e];
        float w = g_w[e];
        float4 v = H4[(size_t)s * 32 + lane];
        acc.x = fmaf(w, v.x, acc.x); acc.y = fmaf(w, v.y, acc.y);
        acc.z = fmaf(w, v.z, acc.z); acc.w = fmaf(w, v.w, acc.w);
    }
    float4 o;
    o.x = di * acc.x; o.y = di * acc.y; o.z = di * acc.z; o.w = di * acc.w;
    O4[(size_t)warp * 32 + lane] = o;
}

// ---- tf32 tensor-core GEMM: [N,128] @ [128,128] + bias, relu ----
// Block: 128 threads (4 warps), tile M=64. Each warp: 16 rows x 128 cols.
// A tile tf32-rounded in padded smem; W (B frags) streamed from global (L1).
__global__ __launch_bounds__(128) void gemm128_tc(const float* __restrict__ W,
                                                  const float* __restrict__ bias,
                                                  int src_is_A) {
    __shared__ float sA[64 * 132];             // pitch 132 -> conflict-free frags
    const float4* A4 = src_is_A ? g_bufA : g_bufB;
    float* Y = (float*)(src_is_A ? g_bufB : g_bufA);

    int tid = threadIdx.x, lane = tid & 31, wid = tid >> 5;
    int base = blockIdx.x * 64;

    // load + tf32-round A tile (64 x 128), zero-pad tail rows
    for (int i = tid; i < 64 * 32; i += 128) {
        int row = i >> 5, q = i & 31;
        int node = base + row;
        float4 v = (node < N_NODES) ? A4[(size_t)node * 32 + q]
                                    : make_float4(0.f, 0.f, 0.f, 0.f);
        float* dst = &sA[row * 132 + q * 4];
        dst[0] = tf32r(v.x); dst[1] = tf32r(v.y);
        dst[2] = tf32r(v.z); dst[3] = tf32r(v.w);
    }
    __syncthreads();

    int gid = lane >> 2, tig = lane & 3;
    int m0 = wid * 16;

    float c[16][4];
#pragma unroll
    for (int nt = 0; nt < 16; nt++)
#pragma unroll
        for (int j = 0; j < 4; j++) c[nt][j] = 0.0f;

#pragma unroll
    for (int kt = 0; kt < 16; kt++) {
        int k0 = kt * 8;
        float a0 = sA[(m0 + gid) * 132 + k0 + tig];
        float a1 = sA[(m0 + gid + 8) * 132 + k0 + tig];
        float a2 = sA[(m0 + gid) * 132 + k0 + tig + 4];
        float a3 = sA[(m0 + gid + 8) * 132 + k0 + tig + 4];
        unsigned ua0 = __float_as_uint(a0), ua1 = __float_as_uint(a1);
        unsigned ua2 = __float_as_uint(a2), ua3 = __float_as_uint(a3);
#pragma unroll
        for (int nt = 0; nt < 16; nt++) {
            int n0 = nt * 8;
            float b0 = tf32r(W[(k0 + tig) * HID + n0 + gid]);
            float b1 = tf32r(W[(k0 + tig + 4) * HID + n0 + gid]);
            asm volatile(
                "mma.sync.aligned.m16n8k8.row.col.f32.tf32.tf32.f32 "
                "{%0,%1,%2,%3}, {%4,%5,%6,%7}, {%8,%9}, {%0,%1,%2,%3};"
                : "+f"(c[nt][0]), "+f"(c[nt][1]), "+f"(c[nt][2]), "+f"(c[nt][3])
                : "r"(ua0), "r"(ua1), "r"(ua2), "r"(ua3),
                  "r"(__float_as_uint(b0)), "r"(__float_as_uint(b1)));
        }
    }

    // epilogue: bias + relu, float2 stores
    int row0 = base + m0 + gid;
    int row1 = row0 + 8;
#pragma unroll
    for (int nt = 0; nt < 16; nt++) {
        int n0 = nt * 8 + 2 * tig;
        float bx = bias[n0], by = bias[n0 + 1];
        if (row0 < N_NODES) {
            float2 o;
            o.x = fmaxf(c[nt][0] + bx, 0.f);
            o.y = fmaxf(c[nt][1] + by, 0.f);
            *(float2*)&Y[(size_t)row0 * HID + n0] = o;
        }
        if (row1 < N_NODES) {
            float2 o;
            o.x = fmaxf(c[nt][2] + bx, 0.f);
            o.y = fmaxf(c[nt][3] + by, 0.f);
            *(float2*)&Y[(size_t)row1 * HID + n0] = o;
        }
    }
}

// mean pool per graph: block per graph, thread per channel (reads g_bufA)
__global__ __launch_bounds__(128) void pool_k() {
    int g = blockIdx.x;
    int c = threadIdx.x;
    int s = g_gstart[g], e = g_gstart[g + 1];
    const float* H = (const float*)g_bufA;
    float acc = 0.0f;
    for (int n = s; n < e; n++) acc += H[(size_t)n * HID + c];
    float inv = 1.0f / fmaxf((float)(e - s), 1.0f);
    g_pool[g * HID + c] = acc * inv;
}

// [512,128] @ [128,64] + bout -> out  (fp32)
__global__ __launch_bounds__(64) void head_k(const float* __restrict__ Wout,
                                             const float* __restrict__ bout,
                                             float* __restrict__ out) {
    int g = blockIdx.x;
    int o = threadIdx.x;
    float acc = bout[o];
#pragma unroll 8
    for (int c = 0; c < HID; c++)
        acc = fmaf(g_pool[g * HID + c], Wout[c * OUT_F + o], acc);
    out[g * OUT_F + o] = acc;
}

// ---------------- launch (kernel launches ONLY — graph-capture safe) ----------------
extern "C" void kernel_launch(void* const* d_in, const int* in_sizes, int n_in,
                              void* d_out, int out_size) {
    const float* x     = (const float*)d_in[0];
    const int*   ei    = (const int*)d_in[1];    // int32 (JAX x64 disabled)
    const int*   batch = (const int*)d_in[2];    // int32
    const float* W1 = (const float*)d_in[3];
    const float* b1 = (const float*)d_in[4];
    const float* W2 = (const float*)d_in[5];
    const float* b2 = (const float*)d_in[6];
    const float* W3 = (const float*)d_in[7];
    const float* b3 = (const float*)d_in[8];
    const float* Wout = (const float*)d_in[9];
    const float* bout = (const float*)d_in[10];
    float* out = (float*)d_out;

    const int NB = 256;
    int nblk_nodes = (N_NODES + NB - 1) / NB;
    int nblk_edges = (N_EDGES + NB - 1) / NB;
    int nblk_warpnode = (N_NODES * 32 + NB - 1) / NB;
    int nblk_tc = (N_NODES + 63) / 64;

    // build CSR + norms
    zero_k<<<nblk_nodes, NB>>>();
    hist_k<<<nblk_edges, NB>>>(ei);
    dinv_k<<<nblk_nodes, NB>>>();
    scan1_k<<<NBLK_SCAN, 1024>>>();
    scan2_k<<<1, 128>>>();
    scan3_k<<<NBLK_SCAN, 1024>>>();
    fill_k<<<nblk_edges, NB>>>(ei);
    bounds_k<<<nblk_nodes, NB>>>(batch);

    // layer 1
    agg20_k<<<nblk_warpnode, NB>>>(x);
    gemm20_k<<<nblk_tc, 128>>>(W1, b1);

    // layer 2: A -(agg)-> B -(tc gemm)-> A
    agg128_k<<<nblk_warpnode, NB>>>(1);
    gemm128_tc<<<nblk_tc, 128>>>(W2, b2, 0);

    // layer 3
    agg128_k<<<nblk_warpnode, NB>>>(1);
    gemm128_tc<<<nblk_tc, 128>>>(W3, b3, 0);

    // pool + head
    pool_k<<<N_GRAPHS, HID>>>();
    head_k<<<N_GRAPHS, OUT_F>>>(Wout, bout, out);
}

// round 7
// speedup vs baseline: 1.2852x; 1.0899x over previous
#include <cuda_runtime.h>
#include <cuda_fp16.h>
#include <math.h>

#define N_NODES  100000
#define N_EDGES  1600000
#define N_GRAPHS 512
#define F_IN     20
#define HID      128
#define OUT_F    64
#define NBLK_SCAN ((N_NODES + 1023) / 1024)   // 98

// ---------------- static device scratch (no runtime allocation) ----------------
__device__ int    g_cnt[N_NODES];
__device__ int    g_fill[N_NODES];
__device__ int    g_rowptr[N_NODES + 1];
__device__ float  g_dinv[N_NODES];
__device__ int    g_col[N_EDGES];
__device__ float  g_w[N_EDGES];
__device__ float  g_aggx[N_NODES * F_IN];
__device__ __align__(16) __half g_hA[(size_t)N_NODES * HID];   // fp16 activations
__device__ float4 g_agg[(size_t)N_NODES * (HID / 4)];          // fp32 aggregate (GEMM A)
__device__ float4 g_fout[(size_t)N_NODES * (HID / 4)];         // fp32 layer-3 out
__device__ int    g_gstart[N_GRAPHS + 1];
__device__ float  g_pool[N_GRAPHS * HID];
__device__ int    g_bsum[NBLK_SCAN];
__device__ int    g_boff[NBLK_SCAN];

// ---------------- helpers ----------------
__device__ __forceinline__ float tf32r(float x) {
    float y;
    asm("cvt.rna.tf32.f32 %0, %1;" : "=f"(y) : "f"(x));
    return y;
}

// ---------------- CSR build ----------------
__global__ void zero_k() {
    int i = blockIdx.x * blockDim.x + threadIdx.x;
    if (i < N_NODES) { g_cnt[i] = 0; g_fill[i] = 0; }
}

__global__ void hist_k(const int* __restrict__ ei) {
    int e = blockIdx.x * blockDim.x + threadIdx.x;
    if (e < N_EDGES) {
        int d = ei[N_EDGES + e];
        atomicAdd(&g_cnt[d], 1);
    }
}

__global__ void dinv_k() {
    int i = blockIdx.x * blockDim.x + threadIdx.x;
    if (i < N_NODES) {
        g_dinv[i] = rsqrtf((float)(g_cnt[i] + 1));  // +1 self loop
    }
}

__global__ __launch_bounds__(1024) void scan1_k() {
    __shared__ int wsum[32];
    int tid = threadIdx.x, lane = tid & 31, wid = tid >> 5;
    int i = blockIdx.x * 1024 + tid;
    int v = (i < N_NODES) ? g_cnt[i] : 0;
    int xv = v;
#pragma unroll
    for (int d = 1; d < 32; d <<= 1) {
        int t = __shfl_up_sync(0xffffffffu, xv, d);
        if (lane >= d) xv += t;
    }
    if (lane == 31) wsum[wid] = xv;
    __syncthreads();
    if (wid == 0) {
        int y = wsum[lane];
#pragma unroll
        for (int d = 1; d < 32; d <<= 1) {
            int t = __shfl_up_sync(0xffffffffu, y, d);
            if (lane >= d) y += t;
        }
        wsum[lane] = y;
    }
    __syncthreads();
    int incl = xv + (wid > 0 ? wsum[wid - 1] : 0);
    if (i < N_NODES) g_rowptr[i] = incl - v;
    if (tid == 1023) g_bsum[blockIdx.x] = incl;
}

__global__ __launch_bounds__(128) void scan2_k() {
    __shared__ int wsum[4];
    int tid = threadIdx.x, lane = tid & 31, wid = tid >> 5;
    int v = (tid < NBLK_SCAN) ? g_bsum[tid] : 0;
    int xv = v;
#pragma unroll
    for (int d = 1; d < 32; d <<= 1) {
        int t = __shfl_up_sync(0xffffffffu, xv, d);
        if (lane >= d) xv += t;
    }
    if (lane == 31) wsum[wid] = xv;
    __syncthreads();
    int pre = 0;
    for (int w = 0; w < wid; w++) pre += wsum[w];
    int incl = xv + pre;
    if (tid < NBLK_SCAN) g_boff[tid] = incl - v;
    if (tid == 127) g_rowptr[N_NODES] = incl;
}

__global__ __launch_bounds__(1024) void scan3_k() {
    int i = blockIdx.x * 1024 + threadIdx.x;
    if (i < N_NODES) g_rowptr[i] += g_boff[blockIdx.x];
}

__global__ void fill_k(const int* __restrict__ ei) {
    int e = blockIdx.x * blockDim.x + threadIdx.x;
    if (e < N_EDGES) {
        int s = ei[e];
        int d = ei[N_EDGES + e];
        int p = g_rowptr[d] + atomicAdd(&g_fill[d], 1);
        g_col[p] = s;
        g_w[p] = g_dinv[s];
    }
}

__global__ void bounds_k(const int* __restrict__ batch) {
    int i = blockIdx.x * blockDim.x + threadIdx.x;
    if (i >= N_NODES) return;
    int b = batch[i];
    if (i == 0) {
        for (int g = 0; g <= b; g++) g_gstart[g] = 0;
    }
    int bn = (i + 1 < N_NODES) ? batch[i + 1] : N_GRAPHS;
    for (int g = b + 1; g <= bn; g++) g_gstart[g] = i + 1;
}

// ---------------- layer 1 ----------------
// warp per node: aggregate raw x (20 dims, fp32)
__global__ __launch_bounds__(256) void agg20_k(const float* __restrict__ x) {
    int warp = (blockIdx.x * blockDim.x + threadIdx.x) >> 5;
    int lane = threadIdx.x & 31;
    if (warp >= N_NODES) return;
    int beg = g_rowptr[warp], end = g_rowptr[warp + 1];
    float di = g_dinv[warp];
    float acc = 0.0f;
    if (lane < F_IN) acc = di * x[(size_t)warp * F_IN + lane];
    for (int e = beg; e < end; e++) {
        int s = g_col[e];
        float w = g_w[e];
        if (lane < F_IN) acc += w * x[(size_t)s * F_IN + lane];
    }
    if (lane < F_IN) g_aggx[(size_t)warp * F_IN + lane] = di * acc;
}

// [N,20] @ [20,128] + b, relu -> g_hA (fp16)
__global__ __launch_bounds__(128) void gemm20_k(const float* __restrict__ W1,
                                                const float* __restrict__ b1) {
    __shared__ float sW[F_IN * HID];
    __shared__ float sB[HID];
    int tid = threadIdx.x;
    for (int i = tid; i < F_IN * HID; i += 128) sW[i] = W1[i];
    sB[tid] = b1[tid];
    __syncthreads();
    int base = blockIdx.x * 64;
    for (int j = 0; j < 64; j++) {
        int node = base + j;
        if (node >= N_NODES) return;
        float acc = sB[tid];
#pragma unroll
        for (int k = 0; k < F_IN; k++)
            acc = fmaf(g_aggx[(size_t)node * F_IN + k], sW[k * HID + tid], acc);
        g_hA[(size_t)node * HID + tid] = __float2half_rn(fmaxf(acc, 0.0f));
    }
}

// ---------------- fp16-gather aggregation: g_hA -> g_agg (fp32) ----------------
// warp per node; each lane owns 4 channels (2 half2 = one 8B load per edge).
__global__ __launch_bounds__(256) void agg128h_k() {
    int warp = (blockIdx.x * blockDim.x + threadIdx.x) >> 5;
    int lane = threadIdx.x & 31;
    if (warp >= N_NODES) return;
    const uint2* H8 = (const uint2*)g_hA;    // 32 x 8B per node
    int beg = g_rowptr[warp], end = g_rowptr[warp + 1];
    float di = g_dinv[warp];
    float4 acc;
    {   // self loop
        uint2 u = H8[(size_t)warp * 32 + lane];
        float2 lo = __half22float2(*(const __half2*)&u.x);
        float2 hi = __half22float2(*(const __half2*)&u.y);
        acc.x = di * lo.x; acc.y = di * lo.y; acc.z = di * hi.x; acc.w = di * hi.y;
    }
    for (int e = beg; e < end; e++) {
        int s = g_col[e];
        float w = g_w[e];
        uint2 u = H8[(size_t)s * 32 + lane];
        float2 lo = __half22float2(*(const __half2*)&u.x);
        float2 hi = __half22float2(*(const __half2*)&u.y);
        acc.x = fmaf(w, lo.x, acc.x); acc.y = fmaf(w, lo.y, acc.y);
        acc.z = fmaf(w, hi.x, acc.z); acc.w = fmaf(w, hi.y, acc.w);
    }
    float4 o;
    o.x = di * acc.x; o.y = di * acc.y; o.z = di * acc.z; o.w = di * acc.w;
    g_agg[(size_t)warp * 32 + lane] = o;
}

// ---- tf32 tensor-core GEMM: g_agg[N,128] @ W[128,128] + bias, relu ----
// out_half=1 -> write fp16 g_hA ; out_half=0 -> write fp32 g_fout
__global__ __launch_bounds__(128) void gemm128_tc(const float* __restrict__ W,
                                                  const float* __restrict__ bias,
                                                  int out_half) {
    __shared__ float sA[64 * 132];             // pitch 132 -> conflict-free frags
    int tid = threadIdx.x, lane = tid & 31, wid = tid >> 5;
    int base = blockIdx.x * 64;

    for (int i = tid; i < 64 * 32; i += 128) {
        int row = i >> 5, q = i & 31;
        int node = base + row;
        float4 v = (node < N_NODES) ? g_agg[(size_t)node * 32 + q]
                                    : make_float4(0.f, 0.f, 0.f, 0.f);
        float* dst = &sA[row * 132 + q * 4];
        dst[0] = tf32r(v.x); dst[1] = tf32r(v.y);
        dst[2] = tf32r(v.z); dst[3] = tf32r(v.w);
    }
    __syncthreads();

    int gid = lane >> 2, tig = lane & 3;
    int m0 = wid * 16;

    float c[16][4];
#pragma unroll
    for (int nt = 0; nt < 16; nt++)
#pragma unroll
        for (int j = 0; j < 4; j++) c[nt][j] = 0.0f;

#pragma unroll
    for (int kt = 0; kt < 16; kt++) {
        int k0 = kt * 8;
        float a0 = sA[(m0 + gid) * 132 + k0 + tig];
        float a1 = sA[(m0 + gid + 8) * 132 + k0 + tig];
        float a2 = sA[(m0 + gid) * 132 + k0 + tig + 4];
        float a3 = sA[(m0 + gid + 8) * 132 + k0 + tig + 4];
        unsigned ua0 = __float_as_uint(a0), ua1 = __float_as_uint(a1);
        unsigned ua2 = __float_as_uint(a2), ua3 = __float_as_uint(a3);
#pragma unroll
        for (int nt = 0; nt < 16; nt++) {
            int n0 = nt * 8;
            float b0 = tf32r(W[(k0 + tig) * HID + n0 + gid]);
            float b1 = tf32r(W[(k0 + tig + 4) * HID + n0 + gid]);
            asm volatile(
                "mma.sync.aligned.m16n8k8.row.col.f32.tf32.tf32.f32 "
                "{%0,%1,%2,%3}, {%4,%5,%6,%7}, {%8,%9}, {%0,%1,%2,%3};"
                : "+f"(c[nt][0]), "+f"(c[nt][1]), "+f"(c[nt][2]), "+f"(c[nt][3])
                : "r"(ua0), "r"(ua1), "r"(ua2), "r"(ua3),
                  "r"(__float_as_uint(b0)), "r"(__float_as_uint(b1)));
        }
    }

    // epilogue: bias + relu
    int row0 = base + m0 + gid;
    int row1 = row0 + 8;
    float* Yf = (float*)g_fout;
#pragma unroll
    for (int nt = 0; nt < 16; nt++) {
        int n0 = nt * 8 + 2 * tig;
        float bx = bias[n0], by = bias[n0 + 1];
        float o0x = fmaxf(c[nt][0] + bx, 0.f), o0y = fmaxf(c[nt][1] + by, 0.f);
        float o1x = fmaxf(c[nt][2] + bx, 0.f), o1y = fmaxf(c[nt][3] + by, 0.f);
        if (out_half) {
            if (row0 < N_NODES)
                *(__half2*)&g_hA[(size_t)row0 * HID + n0] = __floats2half2_rn(o0x, o0y);
            if (row1 < N_NODES)
                *(__half2*)&g_hA[(size_t)row1 * HID + n0] = __floats2half2_rn(o1x, o1y);
        } else {
            if (row0 < N_NODES) { float2 o = {o0x, o0y}; *(float2*)&Yf[(size_t)row0 * HID + n0] = o; }
            if (row1 < N_NODES) { float2 o = {o1x, o1y}; *(float2*)&Yf[(size_t)row1 * HID + n0] = o; }
        }
    }
}

// mean pool per graph (reads fp32 g_fout)
__global__ __launch_bounds__(128) void pool_k() {
    int g = blockIdx.x;
    int c = threadIdx.x;
    int s = g_gstart[g], e = g_gstart[g + 1];
    const float* H = (const float*)g_fout;
    float acc = 0.0f;
    for (int n = s; n < e; n++) acc += H[(size_t)n * HID + c];
    float inv = 1.0f / fmaxf((float)(e - s), 1.0f);
    g_pool[g * HID + c] = acc * inv;
}

// [512,128] @ [128,64] + bout -> out  (fp32)
__global__ __launch_bounds__(64) void head_k(const float* __restrict__ Wout,
                                             const float* __restrict__ bout,
                                             float* __restrict__ out) {
    int g = blockIdx.x;
    int o = threadIdx.x;
    float acc = bout[o];
#pragma unroll 8
    for (int c = 0; c < HID; c++)
        acc = fmaf(g_pool[g * HID + c], Wout[c * OUT_F + o], acc);
    out[g * OUT_F + o] = acc;
}

// ---------------- launch (kernel launches ONLY — graph-capture safe) ----------------
extern "C" void kernel_launch(void* const* d_in, const int* in_sizes, int n_in,
                              void* d_out, int out_size) {
    const float* x     = (const float*)d_in[0];
    const int*   ei    = (const int*)d_in[1];    // int32 (JAX x64 disabled)
    const int*   batch = (const int*)d_in[2];    // int32
    const float* W1 = (const float*)d_in[3];
    const float* b1 = (const float*)d_in[4];
    const float* W2 = (const float*)d_in[5];
    const float* b2 = (const float*)d_in[6];
    const float* W3 = (const float*)d_in[7];
    const float* b3 = (const float*)d_in[8];
    const float* Wout = (const float*)d_in[9];
    const float* bout = (const float*)d_in[10];
    float* out = (float*)d_out;

    const int NB = 256;
    int nblk_nodes = (N_NODES + NB - 1) / NB;
    int nblk_edges = (N_EDGES + NB - 1) / NB;
    int nblk_warpnode = (N_NODES * 32 + NB - 1) / NB;
    int nblk_tc = (N_NODES + 63) / 64;

    // build CSR + norms
    zero_k<<<nblk_nodes, NB>>>();
    hist_k<<<nblk_edges, NB>>>(ei);
    dinv_k<<<nblk_nodes, NB>>>();
    scan1_k<<<NBLK_SCAN, 1024>>>();
    scan2_k<<<1, 128>>>();
    scan3_k<<<NBLK_SCAN, 1024>>>();
    fill_k<<<nblk_edges, NB>>>(ei);
    bounds_k<<<nblk_nodes, NB>>>(batch);

    // layer 1 -> g_hA (fp16)
    agg20_k<<<nblk_warpnode, NB>>>(x);
    gemm20_k<<<nblk_tc, 128>>>(W1, b1);

    // layer 2: g_hA -(agg fp16->fp32)-> g_agg -(tf32 MMA)-> g_hA (fp16)
    agg128h_k<<<nblk_warpnode, NB>>>();
    gemm128_tc<<<nblk_tc, 128>>>(W2, b2, 1);

    // layer 3: g_hA -> g_agg -> g_fout (fp32)
    agg128h_k<<<nblk_warpnode, NB>>>();
    gemm128_tc<<<nblk_tc, 128>>>(W3, b3, 0);

    // pool + head
    pool_k<<<N_GRAPHS, HID>>>();
    head_k<<<N_GRAPHS, OUT_F>>>(Wout, bout, out);
}

// round 10
// speedup vs baseline: 1.6040x; 1.2481x over previous
#include <cuda_runtime.h>
#include <cuda_fp16.h>
#include <math.h>

#define N_NODES  100000
#define N_EDGES  1600000
#define N_GRAPHS 512
#define F_IN     20
#define HID      128
#define OUT_F    64
#define NBLK_SCAN ((N_NODES + 1023) / 1024)   // 98

// ---------------- static device scratch (no runtime allocation) ----------------
__device__ int    g_cnt[N_NODES];
__device__ int    g_fill[N_NODES];
__device__ int    g_rowptr[N_NODES + 1];
__device__ float  g_dinv[N_NODES];
__device__ int    g_col[N_EDGES];
__device__ float  g_w[N_EDGES];
__device__ float  g_aggx[N_NODES * F_IN];
__device__ __align__(16) __half g_hA[(size_t)N_NODES * HID];    // fp16 activations
__device__ __align__(16) __half g_hagg[(size_t)N_NODES * HID];  // fp16 aggregate (GEMM A)
__device__ float4 g_fout[(size_t)N_NODES * (HID / 4)];          // fp32 layer-3 out
__device__ uint2  g_hWp[2][8 * 128 * 4];   // fp16 W in B-fragment layout (32KB each)
__device__ int    g_gstart[N_GRAPHS + 1];
__device__ float  g_pool[N_GRAPHS * HID];
__device__ int    g_bsum[NBLK_SCAN];
__device__ int    g_boff[NBLK_SCAN];

// ---------------- CSR build ----------------
__global__ void zero_k() {
    int i = blockIdx.x * blockDim.x + threadIdx.x;
    if (i < N_NODES) { g_cnt[i] = 0; g_fill[i] = 0; }
}

__global__ void hist_k(const int* __restrict__ ei) {
    int e = blockIdx.x * blockDim.x + threadIdx.x;
    if (e < N_EDGES) {
        int d = ei[N_EDGES + e];
        atomicAdd(&g_cnt[d], 1);
    }
}

__global__ void dinv_k() {
    int i = blockIdx.x * blockDim.x + threadIdx.x;
    if (i < N_NODES) {
        g_dinv[i] = rsqrtf((float)(g_cnt[i] + 1));  // +1 self loop
    }
}

__global__ __launch_bounds__(1024) void scan1_k() {
    __shared__ int wsum[32];
    int tid = threadIdx.x, lane = tid & 31, wid = tid >> 5;
    int i = blockIdx.x * 1024 + tid;
    int v = (i < N_NODES) ? g_cnt[i] : 0;
    int xv = v;
#pragma unroll
    for (int d = 1; d < 32; d <<= 1) {
        int t = __shfl_up_sync(0xffffffffu, xv, d);
        if (lane >= d) xv += t;
    }
    if (lane == 31) wsum[wid] = xv;
    __syncthreads();
    if (wid == 0) {
        int y = wsum[lane];
#pragma unroll
        for (int d = 1; d < 32; d <<= 1) {
            int t = __shfl_up_sync(0xffffffffu, y, d);
            if (lane >= d) y += t;
        }
        wsum[lane] = y;
    }
    __syncthreads();
    int incl = xv + (wid > 0 ? wsum[wid - 1] : 0);
    if (i < N_NODES) g_rowptr[i] = incl - v;
    if (tid == 1023) g_bsum[blockIdx.x] = incl;
}

__global__ __launch_bounds__(128) void scan2_k() {
    __shared__ int wsum[4];
    int tid = threadIdx.x, lane = tid & 31, wid = tid >> 5;
    int v = (tid < NBLK_SCAN) ? g_bsum[tid] : 0;
    int xv = v;
#pragma unroll
    for (int d = 1; d < 32; d <<= 1) {
        int t = __shfl_up_sync(0xffffffffu, xv, d);
        if (lane >= d) xv += t;
    }
    if (lane == 31) wsum[wid] = xv;
    __syncthreads();
    int pre = 0;
    for (int w = 0; w < wid; w++) pre += wsum[w];
    int incl = xv + pre;
    if (tid < NBLK_SCAN) g_boff[tid] = incl - v;
    if (tid == 127) g_rowptr[N_NODES] = incl;
}

__global__ __launch_bounds__(1024) void scan3_k() {
    int i = blockIdx.x * 1024 + threadIdx.x;
    if (i < N_NODES) g_rowptr[i] += g_boff[blockIdx.x];
}

__global__ void fill_k(const int* __restrict__ ei) {
    int e = blockIdx.x * blockDim.x + threadIdx.x;
    if (e < N_EDGES) {
        int s = ei[e];
        int d = ei[N_EDGES + e];
        int p = g_rowptr[d] + atomicAdd(&g_fill[d], 1);
        g_col[p] = s;
        g_w[p] = g_dinv[s];
    }
}

__global__ void bounds_k(const int* __restrict__ batch) {
    int i = blockIdx.x * blockDim.x + threadIdx.x;
    if (i >= N_NODES) return;
    int b = batch[i];
    if (i == 0) {
        for (int g = 0; g <= b; g++) g_gstart[g] = 0;
    }
    int bn = (i + 1 < N_NODES) ? batch[i + 1] : N_GRAPHS;
    for (int g = b + 1; g <= bn; g++) g_gstart[g] = i + 1;
}

// ---- pack W[128][128] fp32 row-major (W[k][n]) into fp16 B-fragment layout ----
// frag (kt, n, tig): halves {W[16kt+2tig][n], W[16kt+2tig+1][n],
//                            W[16kt+2tig+8][n], W[16kt+2tig+9][n]}
__global__ __launch_bounds__(256) void packW_k(const float* __restrict__ W, int slot) {
    int idx = blockIdx.x * 256 + threadIdx.x;     // < 8*128*4 = 4096
    if (idx >= 8 * 128 * 4) return;
    int tig = idx & 3;
    int n   = (idx >> 2) & 127;
    int kt  = idx >> 9;
    int k0  = kt * 16 + 2 * tig;
    __half2 lo = __floats2half2_rn(W[(k0 + 0) * HID + n], W[(k0 + 1) * HID + n]);
    __half2 hi = __floats2half2_rn(W[(k0 + 8) * HID + n], W[(k0 + 9) * HID + n]);
    uint2 u;
    u.x = *(unsigned*)&lo;
    u.y = *(unsigned*)&hi;
    g_hWp[slot][idx] = u;
}

// ---------------- layer 1 ----------------
__global__ __launch_bounds__(256) void agg20_k(const float* __restrict__ x) {
    int warp = (blockIdx.x * blockDim.x + threadIdx.x) >> 5;
    int lane = threadIdx.x & 31;
    if (warp >= N_NODES) return;
    int beg = g_rowptr[warp], end = g_rowptr[warp + 1];
    float di = g_dinv[warp];
    float acc = 0.0f;
    if (lane < F_IN) acc = di * x[(size_t)warp * F_IN + lane];
    for (int e = beg; e < end; e++) {
        int s = g_col[e];
        float w = g_w[e];
        if (lane < F_IN) acc += w * x[(size_t)s * F_IN + lane];
    }
    if (lane < F_IN) g_aggx[(size_t)warp * F_IN + lane] = di * acc;
}

// [N,20] @ [20,128] + b, relu -> g_hA (fp16)
__global__ __launch_bounds__(128) void gemm20_k(const float* __restrict__ W1,
                                                const float* __restrict__ b1) {
    __shared__ float sW[F_IN * HID];
    __shared__ float sB[HID];
    int tid = threadIdx.x;
    for (int i = tid; i < F_IN * HID; i += 128) sW[i] = W1[i];
    sB[tid] = b1[tid];
    __syncthreads();
    int base = blockIdx.x * 64;
    for (int j = 0; j < 64; j++) {
        int node = base + j;
        if (node >= N_NODES) return;
        float acc = sB[tid];
#pragma unroll
        for (int k = 0; k < F_IN; k++)
            acc = fmaf(g_aggx[(size_t)node * F_IN + k], sW[k * HID + tid], acc);
        g_hA[(size_t)node * HID + tid] = __float2half_rn(fmaxf(acc, 0.0f));
    }
}

// ---------------- fp16-gather aggregation: g_hA -> g_hagg (fp16) ----------------
__global__ __launch_bounds__(256) void agg128h_k() {
    int warp = (blockIdx.x * blockDim.x + threadIdx.x) >> 5;
    int lane = threadIdx.x & 31;
    if (warp >= N_NODES) return;
    const uint2* H8 = (const uint2*)g_hA;    // 32 x 8B per node
    int beg = g_rowptr[warp], end = g_rowptr[warp + 1];
    float di = g_dinv[warp];
    float4 acc;
    {   // self loop
        uint2 u = H8[(size_t)warp * 32 + lane];
        float2 lo = __half22float2(*(const __half2*)&u.x);
        float2 hi = __half22float2(*(const __half2*)&u.y);
        acc.x = di * lo.x; acc.y = di * lo.y; acc.z = di * hi.x; acc.w = di * hi.y;
    }
    for (int e = beg; e < end; e++) {
        int s = g_col[e];
        float w = g_w[e];
        uint2 u = H8[(size_t)s * 32 + lane];
        float2 lo = __half22float2(*(const __half2*)&u.x);
        float2 hi = __half22float2(*(const __half2*)&u.y);
        acc.x = fmaf(w, lo.x, acc.x); acc.y = fmaf(w, lo.y, acc.y);
        acc.z = fmaf(w, hi.x, acc.z); acc.w = fmaf(w, hi.y, acc.w);
    }
    __half2 lo = __floats2half2_rn(di * acc.x, di * acc.y);
    __half2 hi = __floats2half2_rn(di * acc.z, di * acc.w);
    uint2 o;
    o.x = *(unsigned*)&lo;
    o.y = *(unsigned*)&hi;
    ((uint2*)g_hagg)[(size_t)warp * 32 + lane] = o;
}

// ---- fp16 tensor-core GEMM: g_hagg[N,128] @ Wp[slot] + bias, relu ----
// Block: 128 threads (4 warps), tile M=64; warp: 16 rows x 128 cols.
// out_half=1 -> g_hA (fp16) ; out_half=0 -> g_fout (fp32)
__global__ __launch_bounds__(128) void gemm128_h(const float* __restrict__ bias,
                                                 int slot, int out_half) {
    __shared__ __half sA[64 * 136];            // pitch 136 halves (272B, 16B-aligned)
    int tid = threadIdx.x, lane = tid & 31, wid = tid >> 5;
    int base = blockIdx.x * 64;

    // load A tile (64 x 128 halves = 1024 uint4), zero-pad tail
    const uint4* A16 = (const uint4*)g_hagg;   // 16 x 8-half chunks per node
    for (int i = tid; i < 64 * 16; i += 128) {
        int row = i >> 4, q = i & 15;
        int node = base + row;
        uint4 v = (node < N_NODES) ? A16[(size_t)node * 16 + q]
                                   : make_uint4(0u, 0u, 0u, 0u);
        *(uint4*)&sA[row * 136 + q * 8] = v;
    }
    __syncthreads();

    int gid = lane >> 2, tig = lane & 3;
    int m0 = wid * 16;
    const uint2* Wp = g_hWp[slot];

    float c[16][4];
#pragma unroll
    for (int nt = 0; nt < 16; nt++)
#pragma unroll
        for (int j = 0; j < 4; j++) c[nt][j] = 0.0f;

#pragma unroll
    for (int kt = 0; kt < 8; kt++) {
        int k0 = kt * 16;
        // A frags (hoisted over nt): row gid/gid+8, k pairs 2tig / 2tig+8
        unsigned a0 = *(const unsigned*)&sA[(m0 + gid) * 136 + k0 + 2 * tig];
        unsigned a1 = *(const unsigned*)&sA[(m0 + gid + 8) * 136 + k0 + 2 * tig];
        unsigned a2 = *(const unsigned*)&sA[(m0 + gid) * 136 + k0 + 2 * tig + 8];
        unsigned a3 = *(const unsigned*)&sA[(m0 + gid + 8) * 136 + k0 + 2 * tig + 8];
        const uint2* wrow = &Wp[(size_t)(kt * 128) * 4 + tig];
#pragma unroll
        for (int nt = 0; nt < 16; nt++) {
            uint2 b = wrow[(nt * 8 + gid) * 4];
            asm volatile(
                "mma.sync.aligned.m16n8k16.row.col.f32.f16.f16.f32 "
                "{%0,%1,%2,%3}, {%4,%5,%6,%7}, {%8,%9}, {%0,%1,%2,%3};"
                : "+f"(c[nt][0]), "+f"(c[nt][1]), "+f"(c[nt][2]), "+f"(c[nt][3])
                : "r"(a0), "r"(a1), "r"(a2), "r"(a3),
                  "r"(b.x), "r"(b.y));
        }
    }

    // epilogue: bias + relu
    int row0 = base + m0 + gid;
    int row1 = row0 + 8;
    float* Yf = (float*)g_fout;
#pragma unroll
    for (int nt = 0; nt < 16; nt++) {
        int n0 = nt * 8 + 2 * tig;
        float bx = bias[n0], by = bias[n0 + 1];
        float o0x = fmaxf(c[nt][0] + bx, 0.f), o0y = fmaxf(c[nt][1] + by, 0.f);
        float o1x = fmaxf(c[nt][2] + bx, 0.f), o1y = fmaxf(c[nt][3] + by, 0.f);
        if (out_half) {
            if (row0 < N_NODES)
                *(__half2*)&g_hA[(size_t)row0 * HID + n0] = __floats2half2_rn(o0x, o0y);
            if (row1 < N_NODES)
                *(__half2*)&g_hA[(size_t)row1 * HID + n0] = __floats2half2_rn(o1x, o1y);
        } else {
            if (row0 < N_NODES) { float2 o = {o0x, o0y}; *(float2*)&Yf[(size_t)row0 * HID + n0] = o; }
            if (row1 < N_NODES) { float2 o = {o1x, o1y}; *(float2*)&Yf[(size_t)row1 * HID + n0] = o; }
        }
    }
}

// mean pool per graph (reads fp32 g_fout)
__global__ __launch_bounds__(128) void pool_k() {
    int g = blockIdx.x;
    int c = threadIdx.x;
    int s = g_gstart[g], e = g_gstart[g + 1];
    const float* H = (const float*)g_fout;
    float acc = 0.0f;
    for (int n = s; n < e; n++) acc += H[(size_t)n * HID + c];
    float inv = 1.0f / fmaxf((float)(e - s), 1.0f);
    g_pool[g * HID + c] = acc * inv;
}

// [512,128] @ [128,64] + bout -> out  (fp32)
__global__ __launch_bounds__(64) void head_k(const float* __restrict__ Wout,
                                             const float* __restrict__ bout,
                                             float* __restrict__ out) {
    int g = blockIdx.x;
    int o = threadIdx.x;
    float acc = bout[o];
#pragma unroll 8
    for (int c = 0; c < HID; c++)
        acc = fmaf(g_pool[g * HID + c], Wout[c * OUT_F + o], acc);
    out[g * OUT_F + o] = acc;
}

// ---------------- launch (kernel launches ONLY — graph-capture safe) ----------------
extern "C" void kernel_launch(void* const* d_in, const int* in_sizes, int n_in,
                              void* d_out, int out_size) {
    const float* x     = (const float*)d_in[0];
    const int*   ei    = (const int*)d_in[1];    // int32 (JAX x64 disabled)
    const int*   batch = (const int*)d_in[2];    // int32
    const float* W1 = (const float*)d_in[3];
    const float* b1 = (const float*)d_in[4];
    const float* W2 = (const float*)d_in[5];
    const float* b2 = (const float*)d_in[6];
    const float* W3 = (const float*)d_in[7];
    const float* b3 = (const float*)d_in[8];
    const float* Wout = (const float*)d_in[9];
    const float* bout = (const float*)d_in[10];
    float* out = (float*)d_out;

    const int NB = 256;
    int nblk_nodes = (N_NODES + NB - 1) / NB;
    int nblk_edges = (N_EDGES + NB - 1) / NB;
    int nblk_warpnode = (N_NODES * 32 + NB - 1) / NB;
    int nblk_tc = (N_NODES + 63) / 64;

    // build CSR + norms; pack weights (independent, early)
    zero_k<<<nblk_nodes, NB>>>();
    hist_k<<<nblk_edges, NB>>>(ei);
    packW_k<<<16, 256>>>(W2, 0);
    packW_k<<<16, 256>>>(W3, 1);
    dinv_k<<<nblk_nodes, NB>>>();
    scan1_k<<<NBLK_SCAN, 1024>>>();
    scan2_k<<<1, 128>>>();
    scan3_k<<<NBLK_SCAN, 1024>>>();
    fill_k<<<nblk_edges, NB>>>(ei);
    bounds_k<<<nblk_nodes, NB>>>(batch);

    // layer 1 -> g_hA (fp16)
    agg20_k<<<nblk_warpnode, NB>>>(x);
    gemm20_k<<<nblk_tc, 128>>>(W1, b1);

    // layer 2: g_hA -> g_hagg -> g_hA
    agg128h_k<<<nblk_warpnode, NB>>>();
    gemm128_h<<<nblk_tc, 128>>>(b2, 0, 1);

    // layer 3: g_hA -> g_hagg -> g_fout (fp32)
    agg128h_k<<<nblk_warpnode, NB>>>();
    gemm128_h<<<nblk_tc, 128>>>(b3, 1, 0);

    // pool + head
    pool_k<<<N_GRAPHS, HID>>>();
    head_k<<<N_GRAPHS, OUT_F>>>(Wout, bout, out);
}

// round 12
// speedup vs baseline: 2.0665x; 1.2883x over previous
#include <cuda_runtime.h>
#include <cuda_fp16.h>
#include <math.h>

#define N_NODES  100000
#define N_EDGES  1600000
#define N_GRAPHS 512
#define F_IN     20
#define HID      128
#define OUT_F    64
#define NBLK_SCAN ((N_NODES + 1023) / 1024)   // 98

// ---------------- static device scratch (no runtime allocation) ----------------
__device__ int    g_cnt[N_NODES];
__device__ int    g_fill[N_NODES];
__device__ int    g_rowptr[N_NODES + 1];
__device__ float  g_dinv[N_NODES];
__device__ int2   g_cw[N_EDGES];            // {src, w as float bits}
__device__ __align__(16) __half g_hx32[(size_t)N_NODES * 32];   // layer-1 agg, fp16 K=32 padded
__device__ __align__(16) __half g_hA[(size_t)N_NODES * HID];    // fp16 activations
__device__ __align__(16) __half g_hagg[(size_t)N_NODES * HID];  // fp16 aggregate (GEMM A)
__device__ uint2  g_hWp[2][8 * 128 * 4];    // W2/W3 fp16 B-frag layout (32KB each)
__device__ uint2  g_hWp1[2 * 128 * 4];      // W1 fp16 B-frag layout (K=32 padded)
__device__ int    g_gstart[N_GRAPHS + 1];
__device__ float  g_pool[N_GRAPHS * HID];
__device__ int    g_bsum[NBLK_SCAN];
__device__ int    g_boff[NBLK_SCAN];

// ---------------- CSR build ----------------
__global__ void zero_k() {
    int i = blockIdx.x * blockDim.x + threadIdx.x;
    if (i < N_NODES) { g_cnt[i] = 0; g_fill[i] = 0; }
}

__global__ void hist_k(const int* __restrict__ ei) {
    int e = blockIdx.x * blockDim.x + threadIdx.x;
    if (e < N_EDGES) {
        int d = ei[N_EDGES + e];
        atomicAdd(&g_cnt[d], 1);
    }
}

__global__ void dinv_k() {
    int i = blockIdx.x * blockDim.x + threadIdx.x;
    if (i < N_NODES) {
        g_dinv[i] = rsqrtf((float)(g_cnt[i] + 1));  // +1 self loop
    }
}

__global__ __launch_bounds__(1024) void scan1_k() {
    __shared__ int wsum[32];
    int tid = threadIdx.x, lane = tid & 31, wid = tid >> 5;
    int i = blockIdx.x * 1024 + tid;
    int v = (i < N_NODES) ? g_cnt[i] : 0;
    int xv = v;
#pragma unroll
    for (int d = 1; d < 32; d <<= 1) {
        int t = __shfl_up_sync(0xffffffffu, xv, d);
        if (lane >= d) xv += t;
    }
    if (lane == 31) wsum[wid] = xv;
    __syncthreads();
    if (wid == 0) {
        int y = wsum[lane];
#pragma unroll
        for (int d = 1; d < 32; d <<= 1) {
            int t = __shfl_up_sync(0xffffffffu, y, d);
            if (lane >= d) y += t;
        }
        wsum[lane] = y;
    }
    __syncthreads();
    int incl = xv + (wid > 0 ? wsum[wid - 1] : 0);
    if (i < N_NODES) g_rowptr[i] = incl - v;
    if (tid == 1023) g_bsum[blockIdx.x] = incl;
}

__global__ __launch_bounds__(128) void scan2_k() {
    __shared__ int wsum[4];
    int tid = threadIdx.x, lane = tid & 31, wid = tid >> 5;
    int v = (tid < NBLK_SCAN) ? g_bsum[tid] : 0;
    int xv = v;
#pragma unroll
    for (int d = 1; d < 32; d <<= 1) {
        int t = __shfl_up_sync(0xffffffffu, xv, d);
        if (lane >= d) xv += t;
    }
    if (lane == 31) wsum[wid] = xv;
    __syncthreads();
    int pre = 0;
    for (int w = 0; w < wid; w++) pre += wsum[w];
    int incl = xv + pre;
    if (tid < NBLK_SCAN) g_boff[tid] = incl - v;
    if (tid == 127) g_rowptr[N_NODES] = incl;
}

__global__ __launch_bounds__(1024) void scan3_k() {
    int i = blockIdx.x * 1024 + threadIdx.x;
    if (i < N_NODES) g_rowptr[i] += g_boff[blockIdx.x];
}

__global__ void fill_k(const int* __restrict__ ei) {
    int e = blockIdx.x * blockDim.x + threadIdx.x;
    if (e < N_EDGES) {
        int s = ei[e];
        int d = ei[N_EDGES + e];
        int p = g_rowptr[d] + atomicAdd(&g_fill[d], 1);
        int2 cw;
        cw.x = s;
        cw.y = __float_as_int(g_dinv[s]);
        g_cw[p] = cw;
    }
}

__global__ void bounds_k(const int* __restrict__ batch) {
    int i = blockIdx.x * blockDim.x + threadIdx.x;
    if (i >= N_NODES) return;
    int b = batch[i];
    if (i == 0) {
        for (int g = 0; g <= b; g++) g_gstart[g] = 0;
    }
    int bn = (i + 1 < N_NODES) ? batch[i + 1] : N_GRAPHS;
    for (int g = b + 1; g <= bn; g++) g_gstart[g] = i + 1;
}

// ---- pack W[128][128] fp32 row-major into fp16 B-fragment layout ----
__global__ __launch_bounds__(256) void packW_k(const float* __restrict__ W, int slot) {
    int idx = blockIdx.x * 256 + threadIdx.x;     // < 8*128*4 = 4096
    if (idx >= 8 * 128 * 4) return;
    int tig = idx & 3;
    int n   = (idx >> 2) & 127;
    int kt  = idx >> 9;
    int k0  = kt * 16 + 2 * tig;
    __half2 lo = __floats2half2_rn(W[(k0 + 0) * HID + n], W[(k0 + 1) * HID + n]);
    __half2 hi = __floats2half2_rn(W[(k0 + 8) * HID + n], W[(k0 + 9) * HID + n]);
    uint2 u;
    u.x = *(unsigned*)&lo;
    u.y = *(unsigned*)&hi;
    g_hWp[slot][idx] = u;
}

// ---- pack W1[20][128] into fp16 B-frag layout, K padded to 32 ----
__global__ __launch_bounds__(256) void packW1_k(const float* __restrict__ W1) {
    int idx = blockIdx.x * 256 + threadIdx.x;     // < 2*128*4 = 1024
    if (idx >= 2 * 128 * 4) return;
    int tig = idx & 3;
    int n   = (idx >> 2) & 127;
    int kt  = idx >> 9;
    int k0  = kt * 16 + 2 * tig;
    float w0 = (k0 + 0 < F_IN) ? W1[(k0 + 0) * HID + n] : 0.f;
    float w1 = (k0 + 1 < F_IN) ? W1[(k0 + 1) * HID + n] : 0.f;
    float w2 = (k0 + 8 < F_IN) ? W1[(k0 + 8) * HID + n] : 0.f;
    float w3 = (k0 + 9 < F_IN) ? W1[(k0 + 9) * HID + n] : 0.f;
    __half2 lo = __floats2half2_rn(w0, w1);
    __half2 hi = __floats2half2_rn(w2, w3);
    uint2 u;
    u.x = *(unsigned*)&lo;
    u.y = *(unsigned*)&hi;
    g_hWp1[idx] = u;
}

// ---------------- layer-1 aggregation: x fp32 -> g_hx32 fp16 [N,32] ----------------
__global__ __launch_bounds__(256) void agg20_k(const float* __restrict__ x) {
    int warp = (blockIdx.x * blockDim.x + threadIdx.x) >> 5;
    int lane = threadIdx.x & 31;
    if (warp >= N_NODES) return;
    int beg = g_rowptr[warp], end = g_rowptr[warp + 1];
    float di = g_dinv[warp];
    float acc = 0.0f;
    if (lane < F_IN) acc = di * x[(size_t)warp * F_IN + lane];
    for (int e = beg; e < end; e++) {
        int2 cw = g_cw[e];
        float w = __int_as_float(cw.y);
        if (lane < F_IN) acc += w * x[(size_t)cw.x * F_IN + lane];
    }
    g_hx32[(size_t)warp * 32 + lane] = __float2half_rn(lane < F_IN ? di * acc : 0.0f);
}

// ---------------- fp16-gather aggregation: g_hA -> g_hagg (fp16) ----------------
__global__ __launch_bounds__(256) void agg128h_k() {
    int warp = (blockIdx.x * blockDim.x + threadIdx.x) >> 5;
    int lane = threadIdx.x & 31;
    if (warp >= N_NODES) return;
    const uint2* H8 = (const uint2*)g_hA;    // 32 x 8B per node
    int beg = g_rowptr[warp], end = g_rowptr[warp + 1];
    float di = g_dinv[warp];
    float4 acc;
    {   // self loop
        uint2 u = H8[(size_t)warp * 32 + lane];
        float2 lo = __half22float2(*(const __half2*)&u.x);
        float2 hi = __half22float2(*(const __half2*)&u.y);
        acc.x = di * lo.x; acc.y = di * lo.y; acc.z = di * hi.x; acc.w = di * hi.y;
    }
    for (int e = beg; e < end; e++) {
        int2 cw = g_cw[e];
        float w = __int_as_float(cw.y);
        uint2 u = H8[(size_t)cw.x * 32 + lane];
        float2 lo = __half22float2(*(const __half2*)&u.x);
        float2 hi = __half22float2(*(const __half2*)&u.y);
        acc.x = fmaf(w, lo.x, acc.x); acc.y = fmaf(w, lo.y, acc.y);
        acc.z = fmaf(w, hi.x, acc.z); acc.w = fmaf(w, hi.y, acc.w);
    }
    __half2 lo = __floats2half2_rn(di * acc.x, di * acc.y);
    __half2 hi = __floats2half2_rn(di * acc.z, di * acc.w);
    uint2 o;
    o.x = *(unsigned*)&lo;
    o.y = *(unsigned*)&hi;
    ((uint2*)g_hagg)[(size_t)warp * 32 + lane] = o;
}

// ---- fp16 MMA GEMM, K=32: g_hx32[N,32] @ g_hWp1 + bias, relu -> g_hA ----
__global__ __launch_bounds__(128) void gemm32_h(const float* __restrict__ bias) {
    __shared__ __half sA[64 * 40];             // pitch 40 halves (80B)
    int tid = threadIdx.x, lane = tid & 31, wid = tid >> 5;
    int base = blockIdx.x * 64;

    const uint4* A16 = (const uint4*)g_hx32;   // 4 x 8-half chunks per node
    for (int i = tid; i < 64 * 4; i += 128) {
        int row = i >> 2, q = i & 3;
        int node = base + row;
        uint4 v = (node < N_NODES) ? A16[(size_t)node * 4 + q]
                                   : make_uint4(0u, 0u, 0u, 0u);
        *(uint4*)&sA[row * 40 + q * 8] = v;
    }
    __syncthreads();

    int gid = lane >> 2, tig = lane & 3;
    int m0 = wid * 16;

    float c[16][4];
#pragma unroll
    for (int nt = 0; nt < 16; nt++)
#pragma unroll
        for (int j = 0; j < 4; j++) c[nt][j] = 0.0f;

#pragma unroll
    for (int kt = 0; kt < 2; kt++) {
        int k0 = kt * 16;
        unsigned a0 = *(const unsigned*)&sA[(m0 + gid) * 40 + k0 + 2 * tig];
        unsigned a1 = *(const unsigned*)&sA[(m0 + gid + 8) * 40 + k0 + 2 * tig];
        unsigned a2 = *(const unsigned*)&sA[(m0 + gid) * 40 + k0 + 2 * tig + 8];
        unsigned a3 = *(const unsigned*)&sA[(m0 + gid + 8) * 40 + k0 + 2 * tig + 8];
        const uint2* wrow = &g_hWp1[(kt * 128) * 4 + tig];
#pragma unroll
        for (int nt = 0; nt < 16; nt++) {
            uint2 b = wrow[(nt * 8 + gid) * 4];
            asm volatile(
                "mma.sync.aligned.m16n8k16.row.col.f32.f16.f16.f32 "
                "{%0,%1,%2,%3}, {%4,%5,%6,%7}, {%8,%9}, {%0,%1,%2,%3};"
                : "+f"(c[nt][0]), "+f"(c[nt][1]), "+f"(c[nt][2]), "+f"(c[nt][3])
                : "r"(a0), "r"(a1), "r"(a2), "r"(a3),
                  "r"(b.x), "r"(b.y));
        }
    }

    int row0 = base + m0 + gid;
    int row1 = row0 + 8;
#pragma unroll
    for (int nt = 0; nt < 16; nt++) {
        int n0 = nt * 8 + 2 * tig;
        float bx = bias[n0], by = bias[n0 + 1];
        if (row0 < N_NODES)
            *(__half2*)&g_hA[(size_t)row0 * HID + n0] =
                __floats2half2_rn(fmaxf(c[nt][0] + bx, 0.f), fmaxf(c[nt][1] + by, 0.f));
        if (row1 < N_NODES)
            *(__half2*)&g_hA[(size_t)row1 * HID + n0] =
                __floats2half2_rn(fmaxf(c[nt][2] + bx, 0.f), fmaxf(c[nt][3] + by, 0.f));
    }
}

// ---- fp16 MMA GEMM, K=128: g_hagg @ g_hWp[slot] + bias, relu -> g_hA ----
__global__ __launch_bounds__(128) void gemm128_h(const float* __restrict__ bias,
                                                 int slot) {
    __shared__ __half sA[64 * 136];            // pitch 136 halves (272B)
    int tid = threadIdx.x, lane = tid & 31, wid = tid >> 5;
    int base = blockIdx.x * 64;

    const uint4* A16 = (const uint4*)g_hagg;   // 16 x 8-half chunks per node
    for (int i = tid; i < 64 * 16; i += 128) {
        int row = i >> 4, q = i & 15;
        int node = base + row;
        uint4 v = (node < N_NODES) ? A16[(size_t)node * 16 + q]
                                   : make_uint4(0u, 0u, 0u, 0u);
        *(uint4*)&sA[row * 136 + q * 8] = v;
    }
    __syncthreads();

    int gid = lane >> 2, tig = lane & 3;
    int m0 = wid * 16;
    const uint2* Wp = g_hWp[slot];

    float c[16][4];
#pragma unroll
    for (int nt = 0; nt < 16; nt++)
#pragma unroll
        for (int j = 0; j < 4; j++) c[nt][j] = 0.0f;

#pragma unroll
    for (int kt = 0; kt < 8; kt++) {
        int k0 = kt * 16;
        unsigned a0 = *(const unsigned*)&sA[(m0 + gid) * 136 + k0 + 2 * tig];
        unsigned a1 = *(const unsigned*)&sA[(m0 + gid + 8) * 136 + k0 + 2 * tig];
        unsigned a2 = *(const unsigned*)&sA[(m0 + gid) * 136 + k0 + 2 * tig + 8];
        unsigned a3 = *(const unsigned*)&sA[(m0 + gid + 8) * 136 + k0 + 2 * tig + 8];
        const uint2* wrow = &Wp[(size_t)(kt * 128) * 4 + tig];
#pragma unroll
        for (int nt = 0; nt < 16; nt++) {
            uint2 b = wrow[(nt * 8 + gid) * 4];
            asm volatile(
                "mma.sync.aligned.m16n8k16.row.col.f32.f16.f16.f32 "
                "{%0,%1,%2,%3}, {%4,%5,%6,%7}, {%8,%9}, {%0,%1,%2,%3};"
                : "+f"(c[nt][0]), "+f"(c[nt][1]), "+f"(c[nt][2]), "+f"(c[nt][3])
                : "r"(a0), "r"(a1), "r"(a2), "r"(a3),
                  "r"(b.x), "r"(b.y));
        }
    }

    int row0 = base + m0 + gid;
    int row1 = row0 + 8;
#pragma unroll
    for (int nt = 0; nt < 16; nt++) {
        int n0 = nt * 8 + 2 * tig;
        float bx = bias[n0], by = bias[n0 + 1];
        if (row0 < N_NODES)
            *(__half2*)&g_hA[(size_t)row0 * HID + n0] =
                __floats2half2_rn(fmaxf(c[nt][0] + bx, 0.f), fmaxf(c[nt][1] + by, 0.f));
        if (row1 < N_NODES)
            *(__half2*)&g_hA[(size_t)row1 * HID + n0] =
                __floats2half2_rn(fmaxf(c[nt][2] + bx, 0.f), fmaxf(c[nt][3] + by, 0.f));
    }
}

// mean pool per graph (reads fp16 g_hA)
__global__ __launch_bounds__(128) void pool_k() {
    int g = blockIdx.x;
    int c = threadIdx.x;
    int s = g_gstart[g], e = g_gstart[g + 1];
    float acc = 0.0f;
    for (int n = s; n < e; n++) acc += __half2float(g_hA[(size_t)n * HID + c]);
    float inv = 1.0f / fmaxf((float)(e - s), 1.0f);
    g_pool[g * HID + c] = acc * inv;
}

// [512,128] @ [128,64] + bout -> out  (fp32)
__global__ __launch_bounds__(64) void head_k(const float* __restrict__ Wout,
                                             const float* __restrict__ bout,
                                             float* __restrict__ out) {
    int g = blockIdx.x;
    int o = threadIdx.x;
    float acc = bout[o];
#pragma unroll 8
    for (int c = 0; c < HID; c++)
        acc = fmaf(g_pool[g * HID + c], Wout[c * OUT_F + o], acc);
    out[g * OUT_F + o] = acc;
}

// ---------------- launch (kernel launches ONLY — graph-capture safe) ----------------
extern "C" void kernel_launch(void* const* d_in, const int* in_sizes, int n_in,
                              void* d_out, int out_size) {
    const float* x     = (const float*)d_in[0];
    const int*   ei    = (const int*)d_in[1];    // int32 (JAX x64 disabled)
    const int*   batch = (const int*)d_in[2];    // int32
    const float* W1 = (const float*)d_in[3];
    const float* b1 = (const float*)d_in[4];
    const float* W2 = (const float*)d_in[5];
    const float* b2 = (const float*)d_in[6];
    const float* W3 = (const float*)d_in[7];
    const float* b3 = (const float*)d_in[8];
    const float* Wout = (const float*)d_in[9];
    const float* bout = (const float*)d_in[10];
    float* out = (float*)d_out;

    const int NB = 256;
    int nblk_nodes = (N_NODES + NB - 1) / NB;
    int nblk_edges = (N_EDGES + NB - 1) / NB;
    int nblk_warpnode = (N_NODES * 32 + NB - 1) / NB;
    int nblk_tc = (N_NODES + 63) / 64;

    // build CSR + norms; pack weights (independent, early)
    zero_k<<<nblk_nodes, NB>>>();
    hist_k<<<nblk_edges, NB>>>(ei);
    packW1_k<<<4, 256>>>(W1);
    packW_k<<<16, 256>>>(W2, 0);
    packW_k<<<16, 256>>>(W3, 1);
    dinv_k<<<nblk_nodes, NB>>>();
    scan1_k<<<NBLK_SCAN, 1024>>>();
    scan2_k<<<1, 128>>>();
    scan3_k<<<NBLK_SCAN, 1024>>>();
    fill_k<<<nblk_edges, NB>>>(ei);
    bounds_k<<<nblk_nodes, NB>>>(batch);

    // layer 1: agg x -> fp16 [N,32], tensor GEMM -> g_hA
    agg20_k<<<nblk_warpnode, NB>>>(x);
    gemm32_h<<<nblk_tc, 128>>>(b1);

    // layer 2: g_hA -> g_hagg -> g_hA
    agg128h_k<<<nblk_warpnode, NB>>>();
    gemm128_h<<<nblk_tc, 128>>>(b2, 0);

    // layer 3: g_hA -> g_hagg -> g_hA
    agg128h_k<<<nblk_warpnode, NB>>>();
    gemm128_h<<<nblk_tc, 128>>>(b3, 1);

    // pool + head
    pool_k<<<N_GRAPHS, HID>>>();
    head_k<<<N_GRAPHS, OUT_F>>>(Wout, bout, out);
}